// round 1
// baseline (speedup 1.0000x reference)
#include <cuda_runtime.h>
#include <cuda_fp16.h>

// ROIAlign(7x7, sampling_ratio=2) + global avg pool, fused and factored.
//
// For each ROI: the sum over all 14x14 bilinear samples of
//   wy(i)*wx(j)*F[y,x] separates into (sum_i wy(i->r)) * (sum_j wx(j->c)),
// i.e. per-ROI row-weight vector a[r] and column-weight vector b[c]
// (b pre-scaled by 1/196 for the mean). Output per (roi, channel) is then
//   sum_r a[r] * sum_c b[c] * F[b, ch, r, c]
// over the ROI bounding box -- contiguous along W, so warps load coalesced.

#define NTHREADS 512
#define NWARPS   16
#define C_CH     256
#define HW       128

__global__ __launch_bounds__(NTHREADS)
void roi_align_pool_kernel(const float* __restrict__ feat,
                           const float* __restrict__ rois,
                           float* __restrict__ out,
                           int n_rois)
{
    __shared__ float a_sh[HW];   // row (H) weights
    __shared__ float b_sh[HW];   // col (W) weights, scaled by 1/196
    __shared__ int rlo_s, rhi_s, clo_s, chi_s, bi_s;

    const int roi = blockIdx.x;
    const int tid = threadIdx.x;

    if (tid == 0) {
        rlo_s = 1 << 30; rhi_s = -1;
        clo_s = 1 << 30; chi_s = -1;
        bi_s = (int)rois[roi * 6 + 0];
        // second output: gt = rois[:,1]
        out[(size_t)n_rois * C_CH + roi] = rois[roi * 6 + 1];
    }
    if (tid < HW) { a_sh[tid] = 0.f; b_sh[tid] = 0.f; }
    __syncthreads();

    // One warp builds the separable weight vectors.
    // Lanes 0..13 handle the 14 y-samples, lanes 16..29 the 14 x-samples.
    if (tid < 32) {
        const bool isY = (tid < 14);
        const bool isX = (tid >= 16 && tid < 30);
        if (isY || isX) {
            const int s = isY ? tid : tid - 16;
            const float cx = rois[roi * 6 + 2];
            const float cy = rois[roi * 6 + 3];
            const float w  = rois[roi * 6 + 4];
            const float h  = rois[roi * 6 + 5];
            // Reference rounds the scaled corners through fp16.
            const float x1 = __half2float(__float2half_rn((cx - 0.5f * w) * 128.f));
            const float x2 = __half2float(__float2half_rn((cx + 0.5f * w) * 128.f));
            const float y1 = __half2float(__float2half_rn((cy - 0.5f * h) * 128.f));
            const float y2 = __half2float(__float2half_rn((cy + 0.5f * h) * 128.f));
            const float rw = fmaxf(x2 - x1, 1.f);
            const float rh = fmaxf(y2 - y1, 1.f);

            const float off   = 0.25f + 0.5f * (float)s;   // p + (sub+0.5)/2
            const float start = isY ? y1 : x1;
            const float ext   = isY ? rh : rw;
            const float coord = start + off * (ext / 7.f);

            const bool valid = (coord > -1.f) && (coord < 128.f);
            if (valid) {
                const float cl = fminf(fmaxf(coord, 0.f), 127.f);
                const int   i0 = (int)floorf(cl);
                const int   i1 = min(i0 + 1, HW - 1);
                const float l  = cl - (float)i0;
                const float hi = 1.f - l;
                if (isY) {
                    atomicAdd(&a_sh[i0], hi);
                    atomicAdd(&a_sh[i1], l);
                    atomicMin(&rlo_s, i0);
                    atomicMax(&rhi_s, i1);
                } else {
                    const float inv = 1.f / 196.f;  // fold in the mean
                    atomicAdd(&b_sh[i0], hi * inv);
                    atomicAdd(&b_sh[i1], l * inv);
                    atomicMin(&clo_s, i0);
                    atomicMax(&chi_s, i1);
                }
            }
        }
    }
    __syncthreads();

    const int rlo = rlo_s, rhi = rhi_s;
    const int clo = clo_s, chi = chi_s;
    const int bi  = bi_s;
    const int warp = tid >> 5;
    const int lane = tid & 31;

    const float* fbase = feat + (size_t)bi * C_CH * (HW * HW);

    // Each warp handles channels warp, warp+16, ... (16 channels each).
    for (int c = warp; c < C_CH; c += NWARPS) {
        float acc = 0.f;
        if (rhi >= rlo && chi >= clo) {
            const float* cbase = fbase + (size_t)c * (HW * HW);
            for (int r = rlo; r <= rhi; ++r) {
                const float ar = a_sh[r];
                if (ar == 0.f) continue;          // warp-uniform skip
                const float* row = cbase + r * HW;
                float psum = 0.f;
                for (int cc = clo + lane; cc <= chi; cc += 32) {
                    psum += b_sh[cc] * __ldg(row + cc);
                }
                acc = fmaf(ar, psum, acc);
            }
        }
        #pragma unroll
        for (int o = 16; o; o >>= 1)
            acc += __shfl_xor_sync(0xffffffffu, acc, o);
        if (lane == 0)
            out[(size_t)roi * C_CH + c] = acc;
    }
}

extern "C" void kernel_launch(void* const* d_in, const int* in_sizes, int n_in,
                              void* d_out, int out_size)
{
    const float* feat = (const float*)d_in[0];   // (4, 256, 128, 128) fp32
    const float* rois = (const float*)d_in[1];   // (N, 6) fp32
    float* out = (float*)d_out;                  // N*256 feats + N gt

    const int n_rois = in_sizes[1] / 6;          // 512
    (void)n_in; (void)out_size;

    roi_align_pool_kernel<<<n_rois, NTHREADS>>>(feat, rois, out, n_rois);
}

// round 2
// speedup vs baseline: 4.0521x; 4.0521x over previous
#include <cuda_runtime.h>
#include <cuda_fp16.h>

// ROIAlign(7x7, sr=2) + global avg pool, separable-weight formulation.
// Per ROI: out[ch] = sum_r a[r] * sum_c b[c] * F[bi, ch, r, c], with a/b the
// y/x bilinear weight marginals (b pre-scaled by 1/196).
//
// R2: issue-bound fix. Each warp processes TWO channels per row iteration:
// lanes 0-15 -> chA, 16-31 -> chB. Each 16-lane group covers the full bbox
// column span with ONE float4 load (max span ~52 cols <= 64). Column weights
// are a per-lane float4 hoisted out of all loops.

#define NTHREADS 256
#define NWARPS   8
#define C_CH     256
#define HW       128

__global__ __launch_bounds__(NTHREADS)
void roi_align_pool_kernel(const float* __restrict__ feat,
                           const float* __restrict__ rois,
                           float* __restrict__ out,
                           int n_rois)
{
    __shared__ float a_sh[HW];        // row (H) weights
    __shared__ float b_sh[192];       // col (W) weights (x 1/196), zero-padded
    __shared__ int rlo_s, rhi_s, clo_s, chi_s, bi_s;

    const int roi = blockIdx.x;
    const int tid = threadIdx.x;

    if (tid == 0) {
        rlo_s = 1 << 30; rhi_s = -1;
        clo_s = 1 << 30; chi_s = -1;
        bi_s = (int)rois[roi * 6 + 0];
        if (blockIdx.y == 0)  // second output: gt = rois[:,1]
            out[(size_t)n_rois * C_CH + roi] = rois[roi * 6 + 1];
    }
    if (tid < 192) {
        if (tid < HW) a_sh[tid] = 0.f;
        b_sh[tid] = 0.f;
    }
    __syncthreads();

    // One warp builds the separable weight vectors.
    if (tid < 32) {
        const bool isY = (tid < 14);
        const bool isX = (tid >= 16 && tid < 30);
        if (isY || isX) {
            const int s = isY ? tid : tid - 16;
            const float cx = rois[roi * 6 + 2];
            const float cy = rois[roi * 6 + 3];
            const float w  = rois[roi * 6 + 4];
            const float h  = rois[roi * 6 + 5];
            // Reference rounds the scaled corners through fp16.
            const float x1 = __half2float(__float2half_rn((cx - 0.5f * w) * 128.f));
            const float x2 = __half2float(__float2half_rn((cx + 0.5f * w) * 128.f));
            const float y1 = __half2float(__float2half_rn((cy - 0.5f * h) * 128.f));
            const float y2 = __half2float(__float2half_rn((cy + 0.5f * h) * 128.f));
            const float rw = fmaxf(x2 - x1, 1.f);
            const float rh = fmaxf(y2 - y1, 1.f);

            const float off   = 0.25f + 0.5f * (float)s;   // p + (sub+0.5)/2
            const float start = isY ? y1 : x1;
            const float ext   = isY ? rh : rw;
            const float coord = start + off * (ext / 7.f);

            if (coord > -1.f && coord < 128.f) {
                const float cl = fminf(fmaxf(coord, 0.f), 127.f);
                const int   i0 = (int)floorf(cl);
                const int   i1 = min(i0 + 1, HW - 1);
                const float l  = cl - (float)i0;
                const float hi = 1.f - l;
                if (isY) {
                    atomicAdd(&a_sh[i0], hi);
                    atomicAdd(&a_sh[i1], l);
                    atomicMin(&rlo_s, i0);
                    atomicMax(&rhi_s, i1);
                } else {
                    const float inv = 1.f / 196.f;  // fold in the mean
                    atomicAdd(&b_sh[i0], hi * inv);
                    atomicAdd(&b_sh[i1], l * inv);
                    atomicMin(&clo_s, i0);
                    atomicMax(&chi_s, i1);
                }
            }
        }
    }
    __syncthreads();

    const int rlo = rlo_s, rhi = rhi_s;
    const int clo = clo_s, chi = chi_s;
    const int warp = tid >> 5;
    const int lane = tid & 31;
    const int g    = lane & 15;       // position within channel group
    const int half = lane >> 4;       // 0 -> chA, 1 -> chB

    const bool nonempty = (rhi >= rlo) && (chi >= clo);

    // Per-lane column chunk + hoisted column weights.
    float4 bw = make_float4(0.f, 0.f, 0.f, 0.f);
    int loadcol = 0;
    if (nonempty) {
        const int base = clo & ~3;
        const int colv = base + 4 * g;
        loadcol = min(colv, HW - 4);                      // clamp: weight is 0 there
        bw = *(const float4*)&b_sh[colv];                 // padded, zero beyond chi
    }

    const float* fbase = feat + (size_t)bi_s * C_CH * (HW * HW);
    const int chBase = blockIdx.y * (C_CH / 2);

    #pragma unroll
    for (int it = 0; it < 8; ++it) {
        const int ch = chBase + it * 16 + warp * 2 + half;
        float acc = 0.f;
        if (nonempty) {
            const float* cbase = fbase + (size_t)ch * (HW * HW) + loadcol;
            #pragma unroll 2
            for (int r = rlo; r <= rhi; ++r) {
                const float ar = a_sh[r];
                if (ar == 0.f) continue;                  // warp-uniform skip
                const float4 f = *(const float4*)(cbase + r * HW);
                float s = bw.x * f.x;
                s = fmaf(bw.y, f.y, s);
                s = fmaf(bw.z, f.z, s);
                s = fmaf(bw.w, f.w, s);
                acc = fmaf(ar, s, acc);
            }
        }
        // reduce within each 16-lane group
        #pragma unroll
        for (int o = 8; o; o >>= 1)
            acc += __shfl_xor_sync(0xffffffffu, acc, o);
        if (g == 0)
            out[(size_t)roi * C_CH + ch] = acc;
    }
}

extern "C" void kernel_launch(void* const* d_in, const int* in_sizes, int n_in,
                              void* d_out, int out_size)
{
    const float* feat = (const float*)d_in[0];   // (4, 256, 128, 128) fp32
    const float* rois = (const float*)d_in[1];   // (N, 6) fp32
    float* out = (float*)d_out;

    const int n_rois = in_sizes[1] / 6;          // 512
    (void)n_in; (void)out_size;

    dim3 grid(n_rois, 2);
    roi_align_pool_kernel<<<grid, NTHREADS>>>(feat, rois, out, n_rois);
}